// round 5
// baseline (speedup 1.0000x reference)
#include <cuda_runtime.h>
#include <cuda_bf16.h>
#include <math.h>
#include <stdint.h>

// CTRNN B=8192, N=512, K=512, 6 unfolds + 1 precompute GEMM.
// bf16 split-precision (hi/lo) GEMM on mma.sync.m16n8k16 (base sm_100 HMMA).
//   P = inputs @ W_in + bias            (mode 0)
//   s' = s + 0.1*(tanh(P + s@W_rec)-s)  (mode 1, x6)
// R5: CTA tile 64x128, warp tile 32x32, 3 CTAs/SM (launch_bounds 256,3),
//     race-free wait->sync->fill->MMA pipeline ordering.

#define BB 8192
#define NN 512
#define KK 512

// ---- scratch (device globals; no allocs allowed) ----
__device__ __nv_bfloat16 g_in_hi[BB * KK];
__device__ __nv_bfloat16 g_in_lo[BB * KK];
__device__ __nv_bfloat16 g_s_hi[2][BB * NN];
__device__ __nv_bfloat16 g_s_lo[2][BB * NN];
__device__ float         g_P[BB * NN];
__device__ __nv_bfloat16 g_WtIn_hi[NN * KK];
__device__ __nv_bfloat16 g_WtIn_lo[NN * KK];
__device__ __nv_bfloat16 g_WtRec_hi[NN * KK];
__device__ __nv_bfloat16 g_WtRec_lo[NN * KK];

// ---- helpers ----
__device__ __forceinline__ uint32_t smem_u32(const void* p) {
    uint32_t a;
    asm("{ .reg .u64 t; cvta.to.shared.u64 t, %1; cvt.u32.u64 %0, t; }" : "=r"(a) : "l"(p));
    return a;
}
__device__ __forceinline__ void cp_async16(uint32_t dst, const void* src) {
    asm volatile("cp.async.cg.shared.global [%0], [%1], 16;" :: "r"(dst), "l"(src));
}
#define CP_COMMIT() asm volatile("cp.async.commit_group;" ::: "memory")
#define CP_WAIT0()  asm volatile("cp.async.wait_group 0;" ::: "memory")

__device__ __forceinline__ void ldm4(uint32_t* r, uint32_t addr) {
    asm volatile("ldmatrix.sync.aligned.m8n8.x4.shared.b16 {%0,%1,%2,%3}, [%4];"
                 : "=r"(r[0]), "=r"(r[1]), "=r"(r[2]), "=r"(r[3]) : "r"(addr));
}
__device__ __forceinline__ void mma16816(float* d, const uint32_t* a, uint32_t b0, uint32_t b1) {
    asm volatile(
        "mma.sync.aligned.m16n8k16.row.col.f32.bf16.bf16.f32 "
        "{%0,%1,%2,%3}, {%4,%5,%6,%7}, {%8,%9}, {%0,%1,%2,%3};"
        : "+f"(d[0]), "+f"(d[1]), "+f"(d[2]), "+f"(d[3])
        : "r"(a[0]), "r"(a[1]), "r"(a[2]), "r"(a[3]), "r"(b0), "r"(b1));
}

// ---- tile geometry ----
#define TM 64
#define TN 128
#define TKC 32                 // K-chunk (bf16)
#define NCHUNK (KK / TKC)      // 16
#define PADB 80                // SMEM row stride bytes (32 bf16 = 64B + 16B pad)
#define TILE_A (64 * PADB)     // 5120
#define TILE_B_SZ (128 * PADB) // 10240
#define OFF_AH 0
#define OFF_AL TILE_A
#define OFF_BH (2 * TILE_A)
#define OFF_BL (2 * TILE_A + TILE_B_SZ)
#define BUF_B (2 * TILE_A + 2 * TILE_B_SZ)   // 30720
#define DSMEM (2 * BUF_B)                    // 61440

// fill ROWS x 32-bf16 tile (padded rows) from global [row0..][kc..kc+32)
template <int ROWS>
__device__ __forceinline__ void fill_tile(uint32_t sbase, const __nv_bfloat16* g,
                                          int row0, int kc, int tid) {
    #pragma unroll
    for (int c = tid; c < ROWS * 4; c += 256) {   // 16B chunks
        int r = c >> 2, q = c & 3;
        cp_async16(sbase + r * PADB + q * 16,
                   g + (size_t)(row0 + r) * 512 + kc + q * 8);
    }
}

__global__ __launch_bounds__(256, 3)
void ctrnn_hmma(const __nv_bfloat16* __restrict__ Ahi,
                const __nv_bfloat16* __restrict__ Alo,
                const __nv_bfloat16* __restrict__ Bhi,   // Wt [N][K]
                const __nv_bfloat16* __restrict__ Blo,
                const float* __restrict__ P,             // mode1 in
                const float* __restrict__ bias,          // mode0 in
                float* __restrict__ Pout,                // mode0 out
                __nv_bfloat16* __restrict__ NShi,        // mode1 outs
                __nv_bfloat16* __restrict__ NSlo,
                float* __restrict__ OutF,
                float* __restrict__ OutF2,
                int mode)
{
    extern __shared__ char dsm_raw[];
    const uint32_t dsm = smem_u32(dsm_raw);

    const int tid = threadIdx.x;
    const int w = tid >> 5;
    const int lane = tid & 31;
    const int warpM = w >> 2;        // 0..1 (32 rows each)
    const int warpN = w & 3;         // 0..3 (32 cols each)
    const int br = blockIdx.y * TM;
    const int bc = blockIdx.x * TN;

    float acc[2][4][4];
    #pragma unroll
    for (int mi = 0; mi < 2; mi++)
        #pragma unroll
        for (int ni = 0; ni < 4; ni++)
            #pragma unroll
            for (int q = 0; q < 4; q++) acc[mi][ni][q] = 0.0f;

    // per-lane ldmatrix byte offsets (within tile)
    const uint32_t aoff = (uint32_t)((warpM * 32 + (lane & 15)) * PADB + (lane >> 4) * 16);
    const uint32_t boff = (uint32_t)((warpN * 32 + (lane >> 4) * 8 + (lane & 7)) * PADB
                                     + ((lane >> 3) & 1) * 16);

    // prologue: fill chunk 0 into buffer 0
    fill_tile<64>(dsm + OFF_AH, Ahi, br, 0, tid);
    fill_tile<64>(dsm + OFF_AL, Alo, br, 0, tid);
    fill_tile<128>(dsm + OFF_BH, Bhi, bc, 0, tid);
    fill_tile<128>(dsm + OFF_BL, Blo, bc, 0, tid);
    CP_COMMIT();

    for (int i = 0; i < NCHUNK; i++) {
        const int b = i & 1;
        // chunk i data ready; barrier also guarantees all warps finished
        // chunk i-1's MMAs on buffer b^1 before we overwrite it below.
        CP_WAIT0();
        __syncthreads();
        if (i + 1 < NCHUNK) {
            uint32_t nb = dsm + (b ^ 1) * BUF_B;
            int kc = (i + 1) * TKC;
            fill_tile<64>(nb + OFF_AH, Ahi, br, kc, tid);
            fill_tile<64>(nb + OFF_AL, Alo, br, kc, tid);
            fill_tile<128>(nb + OFF_BH, Bhi, bc, kc, tid);
            fill_tile<128>(nb + OFF_BL, Blo, bc, kc, tid);
            CP_COMMIT();
        }

        const uint32_t base = dsm + b * BUF_B;
        #pragma unroll
        for (int k2 = 0; k2 < 2; k2++) {
            const uint32_t kb = (uint32_t)(k2 * 32);   // 16 bf16 = 32B

            // phase 1: Ah x Bh  (ah, bh stay live)
            uint32_t ah[2][4], bh[2][4];
            #pragma unroll
            for (int mi = 0; mi < 2; mi++)
                ldm4(ah[mi], base + OFF_AH + aoff + mi * (16 * PADB) + kb);
            #pragma unroll
            for (int p = 0; p < 2; p++)
                ldm4(bh[p], base + OFF_BH + boff + p * (16 * PADB) + kb);
            #pragma unroll
            for (int mi = 0; mi < 2; mi++)
                #pragma unroll
                for (int ni = 0; ni < 4; ni++) {
                    const uint32_t* B = bh[ni >> 1];
                    const int o = (ni & 1) * 2;
                    mma16816(acc[mi][ni], ah[mi], B[o], B[o + 1]);
                }

            // phase 2: Ah x Bl (bl transient)
            {
                uint32_t bl[2][4];
                #pragma unroll
                for (int p = 0; p < 2; p++)
                    ldm4(bl[p], base + OFF_BL + boff + p * (16 * PADB) + kb);
                #pragma unroll
                for (int mi = 0; mi < 2; mi++)
                    #pragma unroll
                    for (int ni = 0; ni < 4; ni++) {
                        const uint32_t* B = bl[ni >> 1];
                        const int o = (ni & 1) * 2;
                        mma16816(acc[mi][ni], ah[mi], B[o], B[o + 1]);
                    }
            }

            // phase 3: Al x Bh (al transient)
            {
                uint32_t al[2][4];
                #pragma unroll
                for (int mi = 0; mi < 2; mi++)
                    ldm4(al[mi], base + OFF_AL + aoff + mi * (16 * PADB) + kb);
                #pragma unroll
                for (int mi = 0; mi < 2; mi++)
                    #pragma unroll
                    for (int ni = 0; ni < 4; ni++) {
                        const uint32_t* B = bh[ni >> 1];
                        const int o = (ni & 1) * 2;
                        mma16816(acc[mi][ni], al[mi], B[o], B[o + 1]);
                    }
            }
        }
        // no trailing sync: next iteration's sync provides the hazard guard
    }

    // ---- fused epilogue ----
    const int tg = lane >> 2;        // 0..7
    const int tp = lane & 3;         // 0..3
    const int row0 = br + warpM * 32;
    const int col0 = bc + warpN * 32;

    #pragma unroll
    for (int mi = 0; mi < 2; mi++) {
        #pragma unroll
        for (int h = 0; h < 2; h++) {
            const int r = row0 + mi * 16 + tg + h * 8;
            #pragma unroll
            for (int ni = 0; ni < 4; ni++) {
                const int c = col0 + ni * 8 + tp * 2;
                const size_t off = (size_t)r * NN + c;
                float v0 = acc[mi][ni][h * 2 + 0];
                float v1 = acc[mi][ni][h * 2 + 1];
                if (mode == 0) {
                    float2 bv = *(const float2*)&bias[c];
                    *(float2*)&Pout[off] = make_float2(v0 + bv.x, v1 + bv.y);
                } else {
                    float2 pv = *(const float2*)&P[off];
                    __nv_bfloat162 shp = *(const __nv_bfloat162*)(Ahi + off);
                    __nv_bfloat162 slp = *(const __nv_bfloat162*)(Alo + off);
                    float s0 = __bfloat162float(shp.x) + __bfloat162float(slp.x);
                    float s1 = __bfloat162float(shp.y) + __bfloat162float(slp.y);
                    float f0 = tanhf(pv.x + v0);
                    float f1 = tanhf(pv.y + v1);
                    float ns0 = s0 + 0.1f * (f0 - s0);
                    float ns1 = s1 + 0.1f * (f1 - s1);
                    __nv_bfloat16 h0 = __float2bfloat16(ns0);
                    __nv_bfloat16 h1 = __float2bfloat16(ns1);
                    __nv_bfloat162 nh, nl;
                    nh.x = h0; nh.y = h1;
                    nl.x = __float2bfloat16(ns0 - __bfloat162float(h0));
                    nl.y = __float2bfloat16(ns1 - __bfloat162float(h1));
                    *(__nv_bfloat162*)(NShi + off) = nh;
                    *(__nv_bfloat162*)(NSlo + off) = nl;
                    if (OutF)  *(float2*)&OutF[off]  = make_float2(ns0, ns1);
                    if (OutF2) *(float2*)&OutF2[off] = make_float2(ns0, ns1);
                }
            }
        }
    }
}

// ---- prep: split fp32 -> bf16 hi/lo for inputs and state ----
__global__ void split_kernel(const float* __restrict__ in, const float* __restrict__ st,
                             __nv_bfloat16* __restrict__ ih, __nv_bfloat16* __restrict__ il,
                             __nv_bfloat16* __restrict__ sh, __nv_bfloat16* __restrict__ sl)
{
    int t = blockIdx.x * blockDim.x + threadIdx.x;
    size_t i = (size_t)t * 4;
    if (i >= (size_t)BB * KK) return;
    float4 vi = *(const float4*)&in[i];
    float4 vs = *(const float4*)&st[i];
    const float* pi = (const float*)&vi;
    const float* ps = (const float*)&vs;
    __nv_bfloat16 a[4], b[4], c[4], d[4];
    #pragma unroll
    for (int j = 0; j < 4; j++) {
        __nv_bfloat16 h = __float2bfloat16(pi[j]);
        a[j] = h; b[j] = __float2bfloat16(pi[j] - __bfloat162float(h));
        __nv_bfloat16 h2 = __float2bfloat16(ps[j]);
        c[j] = h2; d[j] = __float2bfloat16(ps[j] - __bfloat162float(h2));
    }
    *(uint2*)(ih + i) = *(uint2*)a;
    *(uint2*)(il + i) = *(uint2*)b;
    *(uint2*)(sh + i) = *(uint2*)c;
    *(uint2*)(sl + i) = *(uint2*)d;
}

// ---- prep: transpose + split W -> Wt[n][k] hi/lo ----
__global__ void wprep_kernel(const float* __restrict__ W,
                             __nv_bfloat16* __restrict__ WtInHi, __nv_bfloat16* __restrict__ WtInLo,
                             __nv_bfloat16* __restrict__ WtRecHi, __nv_bfloat16* __restrict__ WtRecLo)
{
    int t = blockIdx.x * blockDim.x + threadIdx.x;
    if (t >= NN * KK) return;
    int k = t / NN, n = t % NN;
    int h = blockIdx.y;
    float v = W[(size_t)(k + h * KK) * NN + n];
    __nv_bfloat16 hi = __float2bfloat16(v);
    __nv_bfloat16 lo = __float2bfloat16(v - __bfloat162float(hi));
    size_t o = (size_t)n * KK + k;
    if (h == 0) { WtInHi[o] = hi; WtInLo[o] = lo; }
    else        { WtRecHi[o] = hi; WtRecLo[o] = lo; }
}

extern "C" void kernel_launch(void* const* d_in, const int* in_sizes, int n_in,
                              void* d_out, int out_size)
{
    const float* inputs = (const float*)d_in[0];
    const float* state  = (const float*)d_in[1];
    const float* W      = (const float*)d_in[2];
    const float* bias   = (const float*)d_in[3];
    float* out = (float*)d_out;
    float* out2 = (out_size >= 2 * BB * NN) ? (out + (size_t)BB * NN) : nullptr;

    __nv_bfloat16 *ih, *il, *sh0, *sl0, *sh1, *sl1, *wih, *wil, *wrh, *wrl;
    float* P;
    cudaGetSymbolAddress((void**)&ih,  g_in_hi);
    cudaGetSymbolAddress((void**)&il,  g_in_lo);
    cudaGetSymbolAddress((void**)&sh0, g_s_hi);  sh1 = sh0 + (size_t)BB * NN;
    cudaGetSymbolAddress((void**)&sl0, g_s_lo);  sl1 = sl0 + (size_t)BB * NN;
    cudaGetSymbolAddress((void**)&P,   g_P);
    cudaGetSymbolAddress((void**)&wih, g_WtIn_hi);
    cudaGetSymbolAddress((void**)&wil, g_WtIn_lo);
    cudaGetSymbolAddress((void**)&wrh, g_WtRec_hi);
    cudaGetSymbolAddress((void**)&wrl, g_WtRec_lo);

    cudaFuncSetAttribute(ctrnn_hmma, cudaFuncAttributeMaxDynamicSharedMemorySize, DSMEM);

    split_kernel<<<(BB * KK / 4 + 255) / 256, 256>>>(inputs, state, ih, il, sh0, sl0);
    wprep_kernel<<<dim3((NN * KK + 255) / 256, 2), 256>>>(W, wih, wil, wrh, wrl);

    dim3 grid(NN / TN, BB / TM);   // (4, 128) = 512 CTAs

    ctrnn_hmma<<<grid, 256, DSMEM>>>(ih, il, wih, wil, nullptr, bias, P,
                                     nullptr, nullptr, nullptr, nullptr, 0);
    ctrnn_hmma<<<grid, 256, DSMEM>>>(sh0, sl0, wrh, wrl, P, nullptr, nullptr,
                                     sh1, sl1, nullptr, nullptr, 1);
    ctrnn_hmma<<<grid, 256, DSMEM>>>(sh1, sl1, wrh, wrl, P, nullptr, nullptr,
                                     sh0, sl0, nullptr, nullptr, 1);
    ctrnn_hmma<<<grid, 256, DSMEM>>>(sh0, sl0, wrh, wrl, P, nullptr, nullptr,
                                     sh1, sl1, nullptr, nullptr, 1);
    ctrnn_hmma<<<grid, 256, DSMEM>>>(sh1, sl1, wrh, wrl, P, nullptr, nullptr,
                                     sh0, sl0, nullptr, nullptr, 1);
    ctrnn_hmma<<<grid, 256, DSMEM>>>(sh0, sl0, wrh, wrl, P, nullptr, nullptr,
                                     sh1, sl1, nullptr, nullptr, 1);
    ctrnn_hmma<<<grid, 256, DSMEM>>>(sh1, sl1, wrh, wrl, P, nullptr, nullptr,
                                     sh0, sl0, out, out2, 1);
}

// round 6
// speedup vs baseline: 1.1128x; 1.1128x over previous
#include <cuda_runtime.h>
#include <cuda_bf16.h>
#include <math.h>
#include <stdint.h>

// CTRNN B=8192, N=512, K=512, 6 unfolds + 1 precompute GEMM.
// bf16 split-precision (hi/lo) GEMM on mma.sync.m16n8k16 (base sm_100 HMMA).
//   P = inputs @ W_in + bias            (mode 0)
//   s' = s + 0.1*(tanh(P + s@W_rec)-s)  (mode 1, x6)
// R6: R4 geometry (128x128 CTA, 64x32 warp, 2 CTAs/SM) + 3-stage cp.async
//     ring (wait_group 1, prefetch distance 2) + 64B-row XOR-swizzled SMEM.

#define BB 8192
#define NN 512
#define KK 512

// ---- scratch (device globals; no allocs allowed) ----
__device__ __nv_bfloat16 g_in_hi[BB * KK];
__device__ __nv_bfloat16 g_in_lo[BB * KK];
__device__ __nv_bfloat16 g_s_hi[2][BB * NN];
__device__ __nv_bfloat16 g_s_lo[2][BB * NN];
__device__ float         g_P[BB * NN];
__device__ __nv_bfloat16 g_WtIn_hi[NN * KK];
__device__ __nv_bfloat16 g_WtIn_lo[NN * KK];
__device__ __nv_bfloat16 g_WtRec_hi[NN * KK];
__device__ __nv_bfloat16 g_WtRec_lo[NN * KK];

// ---- helpers ----
__device__ __forceinline__ uint32_t smem_u32(const void* p) {
    uint32_t a;
    asm("{ .reg .u64 t; cvta.to.shared.u64 t, %1; cvt.u32.u64 %0, t; }" : "=r"(a) : "l"(p));
    return a;
}
__device__ __forceinline__ void cp_async16(uint32_t dst, const void* src) {
    asm volatile("cp.async.cg.shared.global [%0], [%1], 16;" :: "r"(dst), "l"(src));
}
#define CP_COMMIT() asm volatile("cp.async.commit_group;" ::: "memory")
#define CP_WAIT1()  asm volatile("cp.async.wait_group 1;" ::: "memory")
#define CP_WAIT0()  asm volatile("cp.async.wait_group 0;" ::: "memory")

__device__ __forceinline__ void ldm4(uint32_t* r, uint32_t addr) {
    asm volatile("ldmatrix.sync.aligned.m8n8.x4.shared.b16 {%0,%1,%2,%3}, [%4];"
                 : "=r"(r[0]), "=r"(r[1]), "=r"(r[2]), "=r"(r[3]) : "r"(addr));
}
__device__ __forceinline__ void mma16816(float* d, const uint32_t* a, uint32_t b0, uint32_t b1) {
    asm volatile(
        "mma.sync.aligned.m16n8k16.row.col.f32.bf16.bf16.f32 "
        "{%0,%1,%2,%3}, {%4,%5,%6,%7}, {%8,%9}, {%0,%1,%2,%3};"
        : "+f"(d[0]), "+f"(d[1]), "+f"(d[2]), "+f"(d[3])
        : "r"(a[0]), "r"(a[1]), "r"(a[2]), "r"(a[3]), "r"(b0), "r"(b1));
}

// ---- tile geometry ----
#define TM 128
#define TN 128
#define TKC 32                 // K-chunk (bf16) = 64B rows
#define NCHUNK (KK / TKC)      // 16
#define NSTAGE 3
// 64B rows, XOR swizzle: quad' = quad ^ ((row>>1)&3); bank-group = (4*row+quad') mod 8
#define TILE_SZ (128 * 64)     // 8192 bytes
#define OFF_AH 0
#define OFF_AL TILE_SZ
#define OFF_BH (2 * TILE_SZ)
#define OFF_BL (3 * TILE_SZ)
#define BUF_B (4 * TILE_SZ)    // 32768
#define DSMEM (NSTAGE * BUF_B) // 98304

// fill a 128-row x 32-bf16 tile (64B swizzled rows) from global [row0..][kc..kc+32)
__device__ __forceinline__ void fill_tile(uint32_t sbase, const __nv_bfloat16* g,
                                          int row0, int kc, int tid) {
    #pragma unroll
    for (int c = tid; c < 512; c += 256) {       // 512 16B chunks
        int r = c >> 2, q = c & 3;
        uint32_t dst = sbase + (uint32_t)(r * 64 + ((q ^ ((r >> 1) & 3)) * 16));
        cp_async16(dst, g + (size_t)(row0 + r) * 512 + kc + q * 8);
    }
}

__global__ __launch_bounds__(256, 2)
void ctrnn_hmma(const __nv_bfloat16* __restrict__ Ahi,
                const __nv_bfloat16* __restrict__ Alo,
                const __nv_bfloat16* __restrict__ Bhi,   // Wt [N][K]
                const __nv_bfloat16* __restrict__ Blo,
                const float* __restrict__ P,             // mode1 in
                const float* __restrict__ bias,          // mode0 in
                float* __restrict__ Pout,                // mode0 out
                __nv_bfloat16* __restrict__ NShi,        // mode1 outs
                __nv_bfloat16* __restrict__ NSlo,
                float* __restrict__ OutF,
                float* __restrict__ OutF2,
                int mode)
{
    extern __shared__ char dsm_raw[];
    const uint32_t dsm = smem_u32(dsm_raw);

    const int tid = threadIdx.x;
    const int w = tid >> 5;
    const int lane = tid & 31;
    const int warpM = w >> 2;        // 0..1 (64 rows each)
    const int warpN = w & 3;         // 0..3 (32 cols each)
    const int br = blockIdx.y * TM;
    const int bc = blockIdx.x * TN;

    float acc[4][4][4];
    #pragma unroll
    for (int mi = 0; mi < 4; mi++)
        #pragma unroll
        for (int ni = 0; ni < 4; ni++)
            #pragma unroll
            for (int q = 0; q < 4; q++) acc[mi][ni][q] = 0.0f;

    // per-lane swizzled ldmatrix offsets within a tile (k2=0); k2=1 => XOR 32.
    uint32_t aoffs[4], boffs[2];
    {
        const int arow_b = (lane & 15);
        const int aq = lane >> 4;              // quad bit0
        #pragma unroll
        for (int mi = 0; mi < 4; mi++) {
            int row = warpM * 64 + mi * 16 + arow_b;
            aoffs[mi] = (uint32_t)(row * 64 + ((aq ^ ((row >> 1) & 3)) * 16));
        }
        const int brow_b = (lane >> 4) * 8 + (lane & 7);
        const int bq = (lane >> 3) & 1;        // quad bit0
        #pragma unroll
        for (int p = 0; p < 2; p++) {
            int row = warpN * 32 + p * 16 + brow_b;
            boffs[p] = (uint32_t)(row * 64 + ((bq ^ ((row >> 1) & 3)) * 16));
        }
    }

    // prologue: fill stages 0 and 1 (chunks 0 and 1), one commit group each
    {
        uint32_t s0 = dsm;
        fill_tile(s0 + OFF_AH, Ahi, br, 0, tid);
        fill_tile(s0 + OFF_AL, Alo, br, 0, tid);
        fill_tile(s0 + OFF_BH, Bhi, bc, 0, tid);
        fill_tile(s0 + OFF_BL, Blo, bc, 0, tid);
        CP_COMMIT();
        uint32_t s1 = dsm + BUF_B;
        fill_tile(s1 + OFF_AH, Ahi, br, TKC, tid);
        fill_tile(s1 + OFF_AL, Alo, br, TKC, tid);
        fill_tile(s1 + OFF_BH, Bhi, bc, TKC, tid);
        fill_tile(s1 + OFF_BL, Blo, bc, TKC, tid);
        CP_COMMIT();
    }

    int stage = 0, fstage = 2;
    for (int i = 0; i < NCHUNK; i++) {
        // chunk i resides in `stage`. Ensure its fill completed; keep the
        // newer prefetch (chunk i+1) in flight. Last chunk: full drain.
        if (i == NCHUNK - 1) { CP_WAIT0(); } else { CP_WAIT1(); }
        // Barrier also guarantees all warps finished chunk i-1's MMAs on
        // stage fstage (== (i-1)%3) before we overwrite it below.
        __syncthreads();
        if (i + 2 < NCHUNK) {
            uint32_t nb = dsm + fstage * BUF_B;
            int kc = (i + 2) * TKC;
            fill_tile(nb + OFF_AH, Ahi, br, kc, tid);
            fill_tile(nb + OFF_AL, Alo, br, kc, tid);
            fill_tile(nb + OFF_BH, Bhi, bc, kc, tid);
            fill_tile(nb + OFF_BL, Blo, bc, kc, tid);
            CP_COMMIT();
        }

        const uint32_t base = dsm + stage * BUF_B;
        #pragma unroll
        for (int k2 = 0; k2 < 2; k2++) {
            const uint32_t kx = (uint32_t)(k2 * 32);   // swizzle-safe XOR select

            // phase 1: Ah x Bh  (ah, bh stay live)
            uint32_t ah[4][4], bh[2][4];
            #pragma unroll
            for (int mi = 0; mi < 4; mi++)
                ldm4(ah[mi], (base + OFF_AH + aoffs[mi]) ^ kx);
            #pragma unroll
            for (int p = 0; p < 2; p++)
                ldm4(bh[p], (base + OFF_BH + boffs[p]) ^ kx);
            #pragma unroll
            for (int mi = 0; mi < 4; mi++)
                #pragma unroll
                for (int ni = 0; ni < 4; ni++) {
                    const uint32_t* B = bh[ni >> 1];
                    const int o = (ni & 1) * 2;
                    mma16816(acc[mi][ni], ah[mi], B[o], B[o + 1]);
                }

            // phase 2: Ah x Bl (bl transient)
            {
                uint32_t bl[2][4];
                #pragma unroll
                for (int p = 0; p < 2; p++)
                    ldm4(bl[p], (base + OFF_BL + boffs[p]) ^ kx);
                #pragma unroll
                for (int mi = 0; mi < 4; mi++)
                    #pragma unroll
                    for (int ni = 0; ni < 4; ni++) {
                        const uint32_t* B = bl[ni >> 1];
                        const int o = (ni & 1) * 2;
                        mma16816(acc[mi][ni], ah[mi], B[o], B[o + 1]);
                    }
            }

            // phase 3: Al x Bh (al transient)
            {
                uint32_t al[4][4];
                #pragma unroll
                for (int mi = 0; mi < 4; mi++)
                    ldm4(al[mi], (base + OFF_AL + aoffs[mi]) ^ kx);
                #pragma unroll
                for (int mi = 0; mi < 4; mi++)
                    #pragma unroll
                    for (int ni = 0; ni < 4; ni++) {
                        const uint32_t* B = bh[ni >> 1];
                        const int o = (ni & 1) * 2;
                        mma16816(acc[mi][ni], al[mi], B[o], B[o + 1]);
                    }
            }
        }
        stage = (stage + 1 == NSTAGE) ? 0 : stage + 1;
        fstage = (fstage + 1 == NSTAGE) ? 0 : fstage + 1;
    }

    // ---- fused epilogue ----
    const int tg = lane >> 2;        // 0..7
    const int tp = lane & 3;         // 0..3
    const int row0 = br + warpM * 64;
    const int col0 = bc + warpN * 32;

    #pragma unroll
    for (int mi = 0; mi < 4; mi++) {
        #pragma unroll
        for (int h = 0; h < 2; h++) {
            const int r = row0 + mi * 16 + tg + h * 8;
            #pragma unroll
            for (int ni = 0; ni < 4; ni++) {
                const int c = col0 + ni * 8 + tp * 2;
                const size_t off = (size_t)r * NN + c;
                float v0 = acc[mi][ni][h * 2 + 0];
                float v1 = acc[mi][ni][h * 2 + 1];
                if (mode == 0) {
                    float2 bv = *(const float2*)&bias[c];
                    *(float2*)&Pout[off] = make_float2(v0 + bv.x, v1 + bv.y);
                } else {
                    float2 pv = *(const float2*)&P[off];
                    __nv_bfloat162 shp = *(const __nv_bfloat162*)(Ahi + off);
                    __nv_bfloat162 slp = *(const __nv_bfloat162*)(Alo + off);
                    float s0 = __bfloat162float(shp.x) + __bfloat162float(slp.x);
                    float s1 = __bfloat162float(shp.y) + __bfloat162float(slp.y);
                    float f0 = tanhf(pv.x + v0);
                    float f1 = tanhf(pv.y + v1);
                    float ns0 = s0 + 0.1f * (f0 - s0);
                    float ns1 = s1 + 0.1f * (f1 - s1);
                    __nv_bfloat16 h0 = __float2bfloat16(ns0);
                    __nv_bfloat16 h1 = __float2bfloat16(ns1);
                    __nv_bfloat162 nh, nl;
                    nh.x = h0; nh.y = h1;
                    nl.x = __float2bfloat16(ns0 - __bfloat162float(h0));
                    nl.y = __float2bfloat16(ns1 - __bfloat162float(h1));
                    *(__nv_bfloat162*)(NShi + off) = nh;
                    *(__nv_bfloat162*)(NSlo + off) = nl;
                    if (OutF)  *(float2*)&OutF[off]  = make_float2(ns0, ns1);
                    if (OutF2) *(float2*)&OutF2[off] = make_float2(ns0, ns1);
                }
            }
        }
    }
}

// ---- prep: split fp32 -> bf16 hi/lo for inputs and state ----
__global__ void split_kernel(const float* __restrict__ in, const float* __restrict__ st,
                             __nv_bfloat16* __restrict__ ih, __nv_bfloat16* __restrict__ il,
                             __nv_bfloat16* __restrict__ sh, __nv_bfloat16* __restrict__ sl)
{
    int t = blockIdx.x * blockDim.x + threadIdx.x;
    size_t i = (size_t)t * 4;
    if (i >= (size_t)BB * KK) return;
    float4 vi = *(const float4*)&in[i];
    float4 vs = *(const float4*)&st[i];
    const float* pi = (const float*)&vi;
    const float* ps = (const float*)&vs;
    __nv_bfloat16 a[4], b[4], c[4], d[4];
    #pragma unroll
    for (int j = 0; j < 4; j++) {
        __nv_bfloat16 h = __float2bfloat16(pi[j]);
        a[j] = h; b[j] = __float2bfloat16(pi[j] - __bfloat162float(h));
        __nv_bfloat16 h2 = __float2bfloat16(ps[j]);
        c[j] = h2; d[j] = __float2bfloat16(ps[j] - __bfloat162float(h2));
    }
    *(uint2*)(ih + i) = *(uint2*)a;
    *(uint2*)(il + i) = *(uint2*)b;
    *(uint2*)(sh + i) = *(uint2*)c;
    *(uint2*)(sl + i) = *(uint2*)d;
}

// ---- prep: transpose + split W -> Wt[n][k] hi/lo ----
__global__ void wprep_kernel(const float* __restrict__ W,
                             __nv_bfloat16* __restrict__ WtInHi, __nv_bfloat16* __restrict__ WtInLo,
                             __nv_bfloat16* __restrict__ WtRecHi, __nv_bfloat16* __restrict__ WtRecLo)
{
    int t = blockIdx.x * blockDim.x + threadIdx.x;
    if (t >= NN * KK) return;
    int k = t / NN, n = t % NN;
    int h = blockIdx.y;
    float v = W[(size_t)(k + h * KK) * NN + n];
    __nv_bfloat16 hi = __float2bfloat16(v);
    __nv_bfloat16 lo = __float2bfloat16(v - __bfloat162float(hi));
    size_t o = (size_t)n * KK + k;
    if (h == 0) { WtInHi[o] = hi; WtInLo[o] = lo; }
    else        { WtRecHi[o] = hi; WtRecLo[o] = lo; }
}

extern "C" void kernel_launch(void* const* d_in, const int* in_sizes, int n_in,
                              void* d_out, int out_size)
{
    const float* inputs = (const float*)d_in[0];
    const float* state  = (const float*)d_in[1];
    const float* W      = (const float*)d_in[2];
    const float* bias   = (const float*)d_in[3];
    float* out = (float*)d_out;
    float* out2 = (out_size >= 2 * BB * NN) ? (out + (size_t)BB * NN) : nullptr;

    __nv_bfloat16 *ih, *il, *sh0, *sl0, *sh1, *sl1, *wih, *wil, *wrh, *wrl;
    float* P;
    cudaGetSymbolAddress((void**)&ih,  g_in_hi);
    cudaGetSymbolAddress((void**)&il,  g_in_lo);
    cudaGetSymbolAddress((void**)&sh0, g_s_hi);  sh1 = sh0 + (size_t)BB * NN;
    cudaGetSymbolAddress((void**)&sl0, g_s_lo);  sl1 = sl0 + (size_t)BB * NN;
    cudaGetSymbolAddress((void**)&P,   g_P);
    cudaGetSymbolAddress((void**)&wih, g_WtIn_hi);
    cudaGetSymbolAddress((void**)&wil, g_WtIn_lo);
    cudaGetSymbolAddress((void**)&wrh, g_WtRec_hi);
    cudaGetSymbolAddress((void**)&wrl, g_WtRec_lo);

    cudaFuncSetAttribute(ctrnn_hmma, cudaFuncAttributeMaxDynamicSharedMemorySize, DSMEM);

    split_kernel<<<(BB * KK / 4 + 255) / 256, 256>>>(inputs, state, ih, il, sh0, sl0);
    wprep_kernel<<<dim3((NN * KK + 255) / 256, 2), 256>>>(W, wih, wil, wrh, wrl);

    dim3 grid(NN / TN, BB / TM);   // (4, 64) = 256 CTAs

    ctrnn_hmma<<<grid, 256, DSMEM>>>(ih, il, wih, wil, nullptr, bias, P,
                                     nullptr, nullptr, nullptr, nullptr, 0);
    ctrnn_hmma<<<grid, 256, DSMEM>>>(sh0, sl0, wrh, wrl, P, nullptr, nullptr,
                                     sh1, sl1, nullptr, nullptr, 1);
    ctrnn_hmma<<<grid, 256, DSMEM>>>(sh1, sl1, wrh, wrl, P, nullptr, nullptr,
                                     sh0, sl0, nullptr, nullptr, 1);
    ctrnn_hmma<<<grid, 256, DSMEM>>>(sh0, sl0, wrh, wrl, P, nullptr, nullptr,
                                     sh1, sl1, nullptr, nullptr, 1);
    ctrnn_hmma<<<grid, 256, DSMEM>>>(sh1, sl1, wrh, wrl, P, nullptr, nullptr,
                                     sh0, sl0, nullptr, nullptr, 1);
    ctrnn_hmma<<<grid, 256, DSMEM>>>(sh0, sl0, wrh, wrl, P, nullptr, nullptr,
                                     sh1, sl1, nullptr, nullptr, 1);
    ctrnn_hmma<<<grid, 256, DSMEM>>>(sh1, sl1, wrh, wrl, P, nullptr, nullptr,
                                     sh0, sl0, out, out2, 1);
}